// round 1
// baseline (speedup 1.0000x reference)
#include <cuda_runtime.h>
#include <cuda_bf16.h>

// ---------------------------------------------------------------------------
// GCN forward:
//   h = features @ W1 + db1
//   h = spmm(A, h)                (b1 dropped: constant cancels in BN)
//   h = relu(bn(h; g1, be1))
//   h = h @ W2
//   h = spmm(A, h)                (b2 dropped likewise)
//   h = relu(bn(h; g2, be2))
//   out = h[idx] @ Wf + bf        (final GEMM only on gathered rows)
// ---------------------------------------------------------------------------

#define NMAX 50000
#define FDIM 256
#define EPSV 1e-5f

__device__ float g_buf0[(size_t)NMAX * FDIM];
__device__ float g_buf1[(size_t)NMAX * FDIM];
__device__ float g_sum[FDIM];
__device__ float g_sumsq[FDIM];
__device__ float g_scale[FDIM];
__device__ float g_shift[FDIM];

// ---------------------------------------------------------------------------
// Zero an accumulation buffer + the BN stats arrays.
// ---------------------------------------------------------------------------
__global__ void zero_kernel(float4* __restrict__ buf, long n4) {
    long i = (long)blockIdx.x * blockDim.x + threadIdx.x;
    long stride = (long)gridDim.x * blockDim.x;
    for (; i < n4; i += stride) buf[i] = make_float4(0.f, 0.f, 0.f, 0.f);
    if (blockIdx.x == 0 && threadIdx.x < FDIM) {
        g_sum[threadIdx.x] = 0.f;
        g_sumsq[threadIdx.x] = 0.f;
    }
}

// ---------------------------------------------------------------------------
// SpMM: out[rows[e]] += edge_vals[e] * x[cols[e]]   (one warp per edge)
// Uses vectorized red.global.add.v4.f32 (sm_90+) — 4x fewer red ops than
// scalar atomicAdd, which would be LSU-issue-bound at ~1ms.
// ---------------------------------------------------------------------------
__global__ __launch_bounds__(256) void spmm_kernel(
    const float* __restrict__ x, const float* __restrict__ ev,
    const int* __restrict__ er, const int* __restrict__ ec,
    float* __restrict__ out, int E)
{
    int e = blockIdx.x * 8 + (threadIdx.x >> 5);
    if (e >= E) return;
    int lane = threadIdx.x & 31;
    int r = __ldg(er + e);
    int c = __ldg(ec + e);
    float w = __ldg(ev + e);
    const float4* src = reinterpret_cast<const float4*>(x + (size_t)c * FDIM);
    float4* dst = reinterpret_cast<float4*>(out + (size_t)r * FDIM);
    float4 v0 = __ldg(src + lane);
    float4 v1 = __ldg(src + lane + 32);
    asm volatile("red.global.add.v4.f32 [%0], {%1,%2,%3,%4};"
                 :: "l"(dst + lane),
                    "f"(v0.x * w), "f"(v0.y * w), "f"(v0.z * w), "f"(v0.w * w)
                 : "memory");
    asm volatile("red.global.add.v4.f32 [%0], {%1,%2,%3,%4};"
                 :: "l"(dst + lane + 32),
                    "f"(v1.x * w), "f"(v1.y * w), "f"(v1.z * w), "f"(v1.w * w)
                 : "memory");
}

// ---------------------------------------------------------------------------
// Column-wise sum / sum-of-squares over M rows (for BatchNorm stats).
// Thread t owns column t; block strides over rows; final atomicAdd per block.
// ---------------------------------------------------------------------------
__global__ __launch_bounds__(256) void stats_kernel(const float* __restrict__ x, int M) {
    int c = threadIdx.x;
    float s = 0.f, s2 = 0.f;
    for (int r = blockIdx.x; r < M; r += gridDim.x) {
        float v = x[(size_t)r * FDIM + c];
        s += v;
        s2 += v * v;
    }
    atomicAdd(&g_sum[c], s);
    atomicAdd(&g_sumsq[c], s2);
}

// Fold BN into y = x*scale + shift.
__global__ void finalize_kernel(const float* __restrict__ gamma,
                                const float* __restrict__ beta, float invN) {
    int c = threadIdx.x;
    float m = g_sum[c] * invN;
    float var = g_sumsq[c] * invN - m * m;
    float rs = rsqrtf(var + EPSV);
    float sc = rs * gamma[c];
    g_scale[c] = sc;
    g_shift[c] = beta[c] - m * sc;
}

// y = relu(x*scale[col] + shift[col]), vectorized float4.
__global__ __launch_bounds__(256) void bnrelu_kernel(
    const float4* __restrict__ in, float4* __restrict__ out, long n4)
{
    long i = (long)blockIdx.x * blockDim.x + threadIdx.x;
    long stride = (long)gridDim.x * blockDim.x;
    for (; i < n4; i += stride) {
        int c = (int)(i & (FDIM / 4 - 1)) * 4;
        float4 v = in[i];
        v.x = fmaxf(fmaf(v.x, g_scale[c + 0], g_shift[c + 0]), 0.f);
        v.y = fmaxf(fmaf(v.y, g_scale[c + 1], g_shift[c + 1]), 0.f);
        v.z = fmaxf(fmaf(v.z, g_scale[c + 2], g_shift[c + 2]), 0.f);
        v.w = fmaxf(fmaf(v.w, g_scale[c + 3], g_shift[c + 3]), 0.f);
        out[i] = v;
    }
}

// ---------------------------------------------------------------------------
// 64x64-tile fp32 GEMM: C = A @ B (+ bias), optional row-gather on A.
// 16x16 threads, each computing a 4x4 microtile. K-tile = 16.
// A stored transposed in smem for conflict-free float4 reads.
// ---------------------------------------------------------------------------
__global__ __launch_bounds__(256) void gemm64_kernel(
    const float* __restrict__ A, const float* __restrict__ B,
    const float* __restrict__ bias, const int* __restrict__ gather,
    float* __restrict__ C, int M, int Ncols, int K)
{
    __shared__ __align__(16) float As[16][64];
    __shared__ __align__(16) float Bs[16][64];

    int tx = threadIdx.x, ty = threadIdx.y;
    int tid = ty * 16 + tx;
    int row0 = blockIdx.y * 64;
    int col0 = blockIdx.x * 64;

    int arow = tid >> 2, akq = tid & 3;    // A tile loader: 64 rows x 4 float4
    int brow = tid >> 4, bcq = tid & 15;   // B tile loader: 16 rows x 16 float4

    int grow = row0 + arow;
    int asrc_row = -1;
    if (grow < M) asrc_row = gather ? __ldg(gather + grow) : grow;

    float acc[4][4] = {};

    for (int kt = 0; kt < K; kt += 16) {
        float4 av = make_float4(0.f, 0.f, 0.f, 0.f);
        if (asrc_row >= 0)
            av = *reinterpret_cast<const float4*>(A + (size_t)asrc_row * K + kt + akq * 4);
        As[akq * 4 + 0][arow] = av.x;
        As[akq * 4 + 1][arow] = av.y;
        As[akq * 4 + 2][arow] = av.z;
        As[akq * 4 + 3][arow] = av.w;

        float4 bv = *reinterpret_cast<const float4*>(
            B + (size_t)(kt + brow) * Ncols + col0 + bcq * 4);
        *reinterpret_cast<float4*>(&Bs[brow][bcq * 4]) = bv;

        __syncthreads();

        #pragma unroll
        for (int k = 0; k < 16; k++) {
            float4 a = *reinterpret_cast<const float4*>(&As[k][ty * 4]);
            float4 b = *reinterpret_cast<const float4*>(&Bs[k][tx * 4]);
            float ar[4] = {a.x, a.y, a.z, a.w};
            float br[4] = {b.x, b.y, b.z, b.w};
            #pragma unroll
            for (int i = 0; i < 4; i++)
                #pragma unroll
                for (int j = 0; j < 4; j++)
                    acc[i][j] = fmaf(ar[i], br[j], acc[i][j]);
        }
        __syncthreads();
    }

    int cbase = col0 + tx * 4;
    float4 bvec = make_float4(0.f, 0.f, 0.f, 0.f);
    if (bias) {
        bvec.x = bias[cbase + 0];
        bvec.y = bias[cbase + 1];
        bvec.z = bias[cbase + 2];
        bvec.w = bias[cbase + 3];
    }
    #pragma unroll
    for (int i = 0; i < 4; i++) {
        int r = row0 + ty * 4 + i;
        if (r < M) {
            float4 o;
            o.x = acc[i][0] + bvec.x;
            o.y = acc[i][1] + bvec.y;
            o.z = acc[i][2] + bvec.z;
            o.w = acc[i][3] + bvec.w;
            *reinterpret_cast<float4*>(C + (size_t)r * Ncols + cbase) = o;
        }
    }
}

// ---------------------------------------------------------------------------
// Launch sequence (all on default stream; graph-capturable: kernels only).
// ---------------------------------------------------------------------------
extern "C" void kernel_launch(void* const* d_in, const int* in_sizes, int n_in,
                              void* d_out, int out_size) {
    const float* features  = (const float*)d_in[0];
    const float* edge_vals = (const float*)d_in[1];
    const float* W1  = (const float*)d_in[2];
    const float* db1 = (const float*)d_in[3];
    // d_in[4] = b1  : cancels in BatchNorm, unused
    const float* g1  = (const float*)d_in[5];
    const float* be1 = (const float*)d_in[6];
    const float* W2  = (const float*)d_in[7];
    // d_in[8] = b2  : cancels in BatchNorm, unused
    const float* g2  = (const float*)d_in[9];
    const float* be2 = (const float*)d_in[10];
    const float* Wf  = (const float*)d_in[11];
    const float* bf  = (const float*)d_in[12];
    const int* erows = (const int*)d_in[13];
    const int* ecols = (const int*)d_in[14];
    const int* idx   = (const int*)d_in[15];
    float* out = (float*)d_out;

    int N = in_sizes[0] / FDIM;   // 50000
    int E = in_sizes[1];          // 800000
    int M = in_sizes[15];         // 25000
    float invN = 1.0f / (float)N;

    float *b0, *b1;
    cudaGetSymbolAddress((void**)&b0, g_buf0);
    cudaGetSymbolAddress((void**)&b1, g_buf1);

    long n4 = (long)N * (FDIM / 4);
    dim3 blk(16, 16);
    int gy = (N + 63) / 64;
    int spmm_blocks = (E + 7) / 8;

    // layer 1
    gemm64_kernel<<<dim3(FDIM / 64, gy), blk>>>(features, W1, db1, nullptr, b0, N, FDIM, FDIM);
    zero_kernel<<<4096, 256>>>((float4*)b1, n4);
    spmm_kernel<<<spmm_blocks, 256>>>(b0, edge_vals, erows, ecols, b1, E);
    stats_kernel<<<512, 256>>>(b1, N);
    finalize_kernel<<<1, 256>>>(g1, be1, invN);
    bnrelu_kernel<<<8192, 256>>>((const float4*)b1, (float4*)b0, n4);

    // layer 2
    gemm64_kernel<<<dim3(FDIM / 64, gy), blk>>>(b0, W2, nullptr, nullptr, b1, N, FDIM, FDIM);
    zero_kernel<<<4096, 256>>>((float4*)b0, n4);
    spmm_kernel<<<spmm_blocks, 256>>>(b1, edge_vals, erows, ecols, b0, E);
    stats_kernel<<<512, 256>>>(b0, N);
    finalize_kernel<<<1, 256>>>(g2, be2, invN);
    bnrelu_kernel<<<8192, 256>>>((const float4*)b0, (float4*)b1, n4);

    // head: only gathered rows
    gemm64_kernel<<<dim3(128 / 64, (M + 63) / 64), blk>>>(b1, Wf, bf, idx, out, M, 128, FDIM);
}

// round 2
// speedup vs baseline: 1.2619x; 1.2619x over previous
#include <cuda_runtime.h>
#include <cuda_bf16.h>

// ---------------------------------------------------------------------------
// GCN forward (tf32 tensor-core GEMMs, BN fused into consumer GEMM A-load):
//   b0 = features @ W1 + db1                      [gemm_tf32]
//   b1 = spmm(A, b0)                              [zero + spmm]
//   scale/shift1 = bn_stats(b1)                   [stats + finalize]
//   b0 = relu(bn1(b1)) @ W2                       [gemm_tf32, bn fused]
//   b1 = spmm(A, b0)                              [zero + spmm]
//   scale/shift2 = bn_stats(b1)                   [stats + finalize]
//   out = relu(bn2(b1))[idx] @ Wf + bf            [gemm_tf32, bn+gather fused]
//  (b1/b2 post-spmm biases cancel inside BatchNorm and are dropped.)
// ---------------------------------------------------------------------------

#define NMAX 50000
#define FDIM 256
#define EPSV 1e-5f

__device__ float g_buf0[(size_t)NMAX * FDIM];
__device__ float g_buf1[(size_t)NMAX * FDIM];
__device__ float g_sum[FDIM];
__device__ float g_sumsq[FDIM];
__device__ float g_scale[FDIM];
__device__ float g_shift[FDIM];

__device__ __forceinline__ unsigned f2tf(float f) {
    unsigned u;
    asm("cvt.rna.tf32.f32 %0, %1;" : "=r"(u) : "f"(f));
    return u;
}

// ---------------------------------------------------------------------------
// Zero accumulation buffer + BN stats arrays.
// ---------------------------------------------------------------------------
__global__ void zero_kernel(float4* __restrict__ buf, long n4) {
    long i = (long)blockIdx.x * blockDim.x + threadIdx.x;
    long stride = (long)gridDim.x * blockDim.x;
    for (; i < n4; i += stride) buf[i] = make_float4(0.f, 0.f, 0.f, 0.f);
    if (blockIdx.x == 0 && threadIdx.x < FDIM) {
        g_sum[threadIdx.x] = 0.f;
        g_sumsq[threadIdx.x] = 0.f;
    }
}

// ---------------------------------------------------------------------------
// SpMM: out[rows[e]] += edge_vals[e] * x[cols[e]]   (one warp per edge)
// red.global.add.v4.f32 -> 4x fewer red ops than scalar atomicAdd.
// ---------------------------------------------------------------------------
__global__ __launch_bounds__(256) void spmm_kernel(
    const float* __restrict__ x, const float* __restrict__ ev,
    const int* __restrict__ er, const int* __restrict__ ec,
    float* __restrict__ out, int E)
{
    int e = blockIdx.x * 8 + (threadIdx.x >> 5);
    if (e >= E) return;
    int lane = threadIdx.x & 31;
    int r = __ldg(er + e);
    int c = __ldg(ec + e);
    float w = __ldg(ev + e);
    const float4* src = reinterpret_cast<const float4*>(x + (size_t)c * FDIM);
    float4* dst = reinterpret_cast<float4*>(out + (size_t)r * FDIM);
    float4 v0 = __ldg(src + lane);
    float4 v1 = __ldg(src + lane + 32);
    asm volatile("red.global.add.v4.f32 [%0], {%1,%2,%3,%4};"
                 :: "l"(dst + lane),
                    "f"(v0.x * w), "f"(v0.y * w), "f"(v0.z * w), "f"(v0.w * w)
                 : "memory");
    asm volatile("red.global.add.v4.f32 [%0], {%1,%2,%3,%4};"
                 :: "l"(dst + lane + 32),
                    "f"(v1.x * w), "f"(v1.y * w), "f"(v1.z * w), "f"(v1.w * w)
                 : "memory");
}

// ---------------------------------------------------------------------------
// BN stats: float4 loads, 4 row-streams per block, 64 float4-columns/thread-row.
// ---------------------------------------------------------------------------
__global__ __launch_bounds__(256) void stats_kernel(const float4* __restrict__ x, int M) {
    int c4 = threadIdx.x & 63;          // float4 column 0..63
    int rl = threadIdx.x >> 6;          // row lane 0..3
    float4 s  = make_float4(0.f, 0.f, 0.f, 0.f);
    float4 q  = make_float4(0.f, 0.f, 0.f, 0.f);
    int stride = gridDim.x * 4;
    #pragma unroll 4
    for (int r = blockIdx.x * 4 + rl; r < M; r += stride) {
        float4 v = __ldg(x + (size_t)r * 64 + c4);
        s.x += v.x; s.y += v.y; s.z += v.z; s.w += v.w;
        q.x += v.x * v.x; q.y += v.y * v.y; q.z += v.z * v.z; q.w += v.w * v.w;
    }
    int c = c4 * 4;
    atomicAdd(&g_sum[c + 0], s.x);  atomicAdd(&g_sum[c + 1], s.y);
    atomicAdd(&g_sum[c + 2], s.z);  atomicAdd(&g_sum[c + 3], s.w);
    atomicAdd(&g_sumsq[c + 0], q.x); atomicAdd(&g_sumsq[c + 1], q.y);
    atomicAdd(&g_sumsq[c + 2], q.z); atomicAdd(&g_sumsq[c + 3], q.w);
}

__global__ void finalize_kernel(const float* __restrict__ gamma,
                                const float* __restrict__ beta, float invN) {
    int c = threadIdx.x;
    float m = g_sum[c] * invN;
    float var = g_sumsq[c] * invN - m * m;
    float rs = rsqrtf(var + EPSV);
    float sc = rs * gamma[c];
    g_scale[c] = sc;
    g_shift[c] = beta[c] - m * sc;
}

// ---------------------------------------------------------------------------
// tf32 tensor-core GEMM: C = op(A) @ B (+ bias)
//   op(A): optional row gather (gather!=null) and/or BN+ReLU (use_bn) on the fly.
// CTA tile 128x64, K-tile 32. 8 warps in 4x2 grid, each warp 32x32 via
// 2x4 m16n8k8 tf32 mma fragments. A/B rounded to tf32 at smem-store time.
// ---------------------------------------------------------------------------
__global__ __launch_bounds__(256) void gemm_tf32(
    const float* __restrict__ A, const float* __restrict__ B,
    const float* __restrict__ bias, const int* __restrict__ gather,
    int use_bn, float* __restrict__ C, int M, int Ncols, int K)
{
    __shared__ __align__(16) float As[128 * 36];  // 128 rows x 32 cols, stride 36
    __shared__ __align__(16) float Bs[32 * 72];   // 32 rows  x 64 cols, stride 72

    int tid = threadIdx.x;
    int lane = tid & 31, w = tid >> 5;
    int wm = w >> 1, wn = w & 1;            // warp grid 4 (M) x 2 (N)
    int g = lane >> 2, tg = lane & 3;       // mma groupID / thread-in-group
    int row0 = blockIdx.y * 128, col0 = blockIdx.x * 64;

    float acc[2][4][4];
    #pragma unroll
    for (int mi = 0; mi < 2; mi++)
        #pragma unroll
        for (int ni = 0; ni < 4; ni++)
            #pragma unroll
            for (int j = 0; j < 4; j++) acc[mi][ni][j] = 0.f;

    // Resolve A source rows for this thread's 4 loader slots once.
    int asrc[4];
    #pragma unroll
    for (int p = 0; p < 4; p++) {
        int idx = tid + p * 256;
        int grow = row0 + (idx >> 3);
        int sr = grow < M ? grow : M - 1;
        if (gather) sr = __ldg(gather + sr);
        asrc[p] = sr;
    }

    for (int kt = 0; kt < K; kt += 32) {
        // --- load A tile (128x32): 4 float4 per thread, bn+tf32 at store ---
        #pragma unroll
        for (int p = 0; p < 4; p++) {
            int idx = tid + p * 256;
            int row = idx >> 3, c4 = idx & 7;
            int cb = kt + c4 * 4;
            float4 v = *reinterpret_cast<const float4*>(A + (size_t)asrc[p] * K + cb);
            if (use_bn) {
                v.x = fmaxf(fmaf(v.x, g_scale[cb + 0], g_shift[cb + 0]), 0.f);
                v.y = fmaxf(fmaf(v.y, g_scale[cb + 1], g_shift[cb + 1]), 0.f);
                v.z = fmaxf(fmaf(v.z, g_scale[cb + 2], g_shift[cb + 2]), 0.f);
                v.w = fmaxf(fmaf(v.w, g_scale[cb + 3], g_shift[cb + 3]), 0.f);
            }
            float4 o;
            o.x = __uint_as_float(f2tf(v.x));
            o.y = __uint_as_float(f2tf(v.y));
            o.z = __uint_as_float(f2tf(v.z));
            o.w = __uint_as_float(f2tf(v.w));
            *reinterpret_cast<float4*>(As + row * 36 + c4 * 4) = o;
        }
        // --- load B tile (32x64): 2 float4 per thread ---
        #pragma unroll
        for (int p = 0; p < 2; p++) {
            int idx = tid + p * 256;
            int row = idx >> 4, c4 = idx & 15;
            float4 v = *reinterpret_cast<const float4*>(
                B + (size_t)(kt + row) * Ncols + col0 + c4 * 4);
            float4 o;
            o.x = __uint_as_float(f2tf(v.x));
            o.y = __uint_as_float(f2tf(v.y));
            o.z = __uint_as_float(f2tf(v.z));
            o.w = __uint_as_float(f2tf(v.w));
            *reinterpret_cast<float4*>(Bs + row * 72 + c4 * 4) = o;
        }
        __syncthreads();

        #pragma unroll
        for (int kk = 0; kk < 4; kk++) {
            unsigned a[2][4], b[4][2];
            #pragma unroll
            for (int mi = 0; mi < 2; mi++) {
                int rb = wm * 32 + mi * 16;
                int kc = kk * 8 + tg;
                a[mi][0] = __float_as_uint(As[(rb + g)     * 36 + kc]);
                a[mi][1] = __float_as_uint(As[(rb + g + 8) * 36 + kc]);
                a[mi][2] = __float_as_uint(As[(rb + g)     * 36 + kc + 4]);
                a[mi][3] = __float_as_uint(As[(rb + g + 8) * 36 + kc + 4]);
            }
            #pragma unroll
            for (int ni = 0; ni < 4; ni++) {
                int col = wn * 32 + ni * 8 + g;
                b[ni][0] = __float_as_uint(Bs[(kk * 8 + tg)     * 72 + col]);
                b[ni][1] = __float_as_uint(Bs[(kk * 8 + tg + 4) * 72 + col]);
            }
            #pragma unroll
            for (int mi = 0; mi < 2; mi++)
                #pragma unroll
                for (int ni = 0; ni < 4; ni++)
                    asm volatile(
                        "mma.sync.aligned.m16n8k8.row.col.f32.tf32.tf32.f32 "
                        "{%0,%1,%2,%3}, {%4,%5,%6,%7}, {%8,%9}, {%0,%1,%2,%3};"
                        : "+f"(acc[mi][ni][0]), "+f"(acc[mi][ni][1]),
                          "+f"(acc[mi][ni][2]), "+f"(acc[mi][ni][3])
                        : "r"(a[mi][0]), "r"(a[mi][1]), "r"(a[mi][2]), "r"(a[mi][3]),
                          "r"(b[ni][0]), "r"(b[ni][1]));
        }
        __syncthreads();
    }

    // --- epilogue: bias add + store (float2 per fragment half) ---
    #pragma unroll
    for (int mi = 0; mi < 2; mi++) {
        int r = row0 + wm * 32 + mi * 16 + g;
        #pragma unroll
        for (int ni = 0; ni < 4; ni++) {
            int c = col0 + wn * 32 + ni * 8 + tg * 2;
            float bx = bias ? __ldg(bias + c) : 0.f;
            float by = bias ? __ldg(bias + c + 1) : 0.f;
            if (r < M) {
                float2 o = make_float2(acc[mi][ni][0] + bx, acc[mi][ni][1] + by);
                *reinterpret_cast<float2*>(C + (size_t)r * Ncols + c) = o;
            }
            if (r + 8 < M) {
                float2 o = make_float2(acc[mi][ni][2] + bx, acc[mi][ni][3] + by);
                *reinterpret_cast<float2*>(C + (size_t)(r + 8) * Ncols + c) = o;
            }
        }
    }
}

// ---------------------------------------------------------------------------
// Launch sequence (graph-capturable: kernels only).
// ---------------------------------------------------------------------------
extern "C" void kernel_launch(void* const* d_in, const int* in_sizes, int n_in,
                              void* d_out, int out_size) {
    const float* features  = (const float*)d_in[0];
    const float* edge_vals = (const float*)d_in[1];
    const float* W1  = (const float*)d_in[2];
    const float* db1 = (const float*)d_in[3];
    // d_in[4] = b1  : cancels in BatchNorm
    const float* g1  = (const float*)d_in[5];
    const float* be1 = (const float*)d_in[6];
    const float* W2  = (const float*)d_in[7];
    // d_in[8] = b2  : cancels in BatchNorm
    const float* g2  = (const float*)d_in[9];
    const float* be2 = (const float*)d_in[10];
    const float* Wf  = (const float*)d_in[11];
    const float* bf  = (const float*)d_in[12];
    const int* erows = (const int*)d_in[13];
    const int* ecols = (const int*)d_in[14];
    const int* idx   = (const int*)d_in[15];
    float* out = (float*)d_out;

    int N = in_sizes[0] / FDIM;   // 50000
    int E = in_sizes[1];          // 800000
    int M = in_sizes[15];         // 25000
    float invN = 1.0f / (float)N;

    float *b0, *b1;
    cudaGetSymbolAddress((void**)&b0, g_buf0);
    cudaGetSymbolAddress((void**)&b1, g_buf1);

    long n4 = (long)N * (FDIM / 4);
    int spmm_blocks = (E + 7) / 8;
    dim3 ggrid(FDIM / 64, (N + 127) / 128);

    // layer 1
    gemm_tf32<<<ggrid, 256>>>(features, W1, db1, nullptr, 0, b0, N, FDIM, FDIM);
    zero_kernel<<<4096, 256>>>((float4*)b1, n4);
    spmm_kernel<<<spmm_blocks, 256>>>(b0, edge_vals, erows, ecols, b1, E);
    stats_kernel<<<592, 256>>>((const float4*)b1, N);
    finalize_kernel<<<1, 256>>>(g1, be1, invN);

    // layer 2 (BN1+ReLU fused into A-load)
    gemm_tf32<<<ggrid, 256>>>(b1, W2, nullptr, nullptr, 1, b0, N, FDIM, FDIM);
    zero_kernel<<<4096, 256>>>((float4*)b1, n4);
    spmm_kernel<<<spmm_blocks, 256>>>(b0, edge_vals, erows, ecols, b1, E);
    stats_kernel<<<592, 256>>>((const float4*)b1, N);
    finalize_kernel<<<1, 256>>>(g2, be2, invN);

    // head (BN2+ReLU + gather fused into A-load)
    gemm_tf32<<<dim3(128 / 64, (M + 127) / 128), 256>>>(
        b1, Wf, bf, idx, 1, out, M, 128, FDIM);
}

// round 3
// speedup vs baseline: 1.9337x; 1.5324x over previous
#include <cuda_runtime.h>
#include <cuda_bf16.h>

// ---------------------------------------------------------------------------
// GCN forward, round 3: CSR-based SpMM with fused BN statistics.
//   CSR build (hist -> scan -> scatter)        [once per launch]
//   b0 = features @ W1 + db1                   [gemm_tf32]
//   b1 = spmm_csr(A, b0)  + bn stats           [spmm_csr, plain stores]
//   scale/shift1                               [finalize, resets stats]
//   b0 = relu(bn1(b1)) @ W2                    [gemm_tf32, bn fused]
//   b1 = spmm_csr(A, b0)  + bn stats           [spmm_csr]
//   scale/shift2                               [finalize]
//   out = relu(bn2(b1))[idx] @ Wf + bf         [gemm_tf32, bn+gather fused]
//  (post-spmm biases b1/b2 cancel inside BatchNorm and are dropped.)
// ---------------------------------------------------------------------------

#define NMAXN 50000
#define EMAX  800000
#define FDIM  256
#define EPSV  1e-5f
#define RPW   10          // rows per warp in spmm_csr

__device__ float g_buf0[(size_t)NMAXN * FDIM];
__device__ float g_buf1[(size_t)NMAXN * FDIM];
__device__ float g_sum[FDIM];
__device__ float g_sumsq[FDIM];
__device__ float g_scale[FDIM];
__device__ float g_shift[FDIM];

__device__ int   g_cnt[NMAXN];       // histogram / temp
__device__ int   g_cursor[NMAXN];    // scatter cursors
__device__ int   g_ptr[NMAXN + 1];   // CSR row pointers
__device__ int   g_ccol[EMAX];       // CSR cols
__device__ float g_cval[EMAX];       // CSR vals

__device__ __forceinline__ unsigned f2tf(float f) {
    unsigned u;
    asm("cvt.rna.tf32.f32 %0, %1;" : "=r"(u) : "f"(f));
    return u;
}

// ---------------------------------------------------------------------------
// CSR build step 1: zero histogram + BN stat accumulators.
// ---------------------------------------------------------------------------
__global__ void init_kernel(int n) {
    int i = blockIdx.x * blockDim.x + threadIdx.x;
    if (i < n) g_cnt[i] = 0;
    if (i < FDIM) { g_sum[i] = 0.f; g_sumsq[i] = 0.f; }
}

// step 2: row histogram
__global__ void hist_kernel(const int* __restrict__ er, int E) {
    int e = blockIdx.x * blockDim.x + threadIdx.x;
    if (e < E) atomicAdd(&g_cnt[er[e]], 1);
}

// step 3: exclusive scan (single block, 1024 threads, chunked)
__global__ __launch_bounds__(1024) void scan_kernel(int n, int E) {
    __shared__ int sdata[1024];
    int tid = threadIdx.x;
    int off = 0;
    for (int base = 0; base < n; base += 1024) {
        int i = base + tid;
        int v = (i < n) ? g_cnt[i] : 0;
        sdata[tid] = v;
        __syncthreads();
        #pragma unroll
        for (int d = 1; d < 1024; d <<= 1) {
            int t = (tid >= d) ? sdata[tid - d] : 0;
            __syncthreads();
            sdata[tid] += t;
            __syncthreads();
        }
        if (i < n) {
            int p = off + sdata[tid] - v;
            g_ptr[i] = p;
            g_cursor[i] = p;
        }
        off += sdata[1023];
        __syncthreads();
    }
    if (tid == 0) g_ptr[n] = E;
}

// step 4: scatter edges into CSR slots
__global__ void scatter_kernel(const int* __restrict__ er, const int* __restrict__ ec,
                               const float* __restrict__ ev, int E) {
    int e = blockIdx.x * blockDim.x + threadIdx.x;
    if (e >= E) return;
    int pos = atomicAdd(&g_cursor[er[e]], 1);
    g_ccol[pos] = ec[e];
    g_cval[pos] = ev[e];
}

// ---------------------------------------------------------------------------
// CSR SpMM with fused BN statistics.
// One warp handles RPW consecutive rows. Row accumulated in registers
// (lane owns float4 columns `lane` and `lane+32`), stored with plain float4
// stores (no atomics, no zero pass). Per-lane stat accumulators are reduced
// across the CTA's 8 warps in smem; one atomic set per CTA.
// ---------------------------------------------------------------------------
__global__ __launch_bounds__(256) void spmm_csr(
    const float4* __restrict__ x, float4* __restrict__ out, int N)
{
    __shared__ __align__(16) float4 sm_s[8][64];
    __shared__ __align__(16) float4 sm_q[8][64];

    int lane = threadIdx.x & 31;
    int w = threadIdx.x >> 5;
    int warp_g = blockIdx.x * 8 + w;
    int r0 = warp_g * RPW;

    float4 s0 = {0,0,0,0}, q0 = {0,0,0,0};
    float4 s1 = {0,0,0,0}, q1 = {0,0,0,0};

    int rend = min(r0 + RPW, N);
    for (int r = r0; r < rend; r++) {
        int e = __ldg(&g_ptr[r]);
        int end = __ldg(&g_ptr[r + 1]);
        float4 a0 = {0,0,0,0}, a1 = {0,0,0,0};
        for (; e + 1 < end; e += 2) {
            int   c0 = __ldg(&g_ccol[e]),     c1 = __ldg(&g_ccol[e + 1]);
            float w0 = __ldg(&g_cval[e]),     w1 = __ldg(&g_cval[e + 1]);
            float4 u0 = __ldg(x + (size_t)c0 * 64 + lane);
            float4 u1 = __ldg(x + (size_t)c0 * 64 + 32 + lane);
            float4 v0 = __ldg(x + (size_t)c1 * 64 + lane);
            float4 v1 = __ldg(x + (size_t)c1 * 64 + 32 + lane);
            a0.x = fmaf(w0, u0.x, fmaf(w1, v0.x, a0.x));
            a0.y = fmaf(w0, u0.y, fmaf(w1, v0.y, a0.y));
            a0.z = fmaf(w0, u0.z, fmaf(w1, v0.z, a0.z));
            a0.w = fmaf(w0, u0.w, fmaf(w1, v0.w, a0.w));
            a1.x = fmaf(w0, u1.x, fmaf(w1, v1.x, a1.x));
            a1.y = fmaf(w0, u1.y, fmaf(w1, v1.y, a1.y));
            a1.z = fmaf(w0, u1.z, fmaf(w1, v1.z, a1.z));
            a1.w = fmaf(w0, u1.w, fmaf(w1, v1.w, a1.w));
        }
        if (e < end) {
            int   c0 = __ldg(&g_ccol[e]);
            float w0 = __ldg(&g_cval[e]);
            float4 u0 = __ldg(x + (size_t)c0 * 64 + lane);
            float4 u1 = __ldg(x + (size_t)c0 * 64 + 32 + lane);
            a0.x = fmaf(w0, u0.x, a0.x); a0.y = fmaf(w0, u0.y, a0.y);
            a0.z = fmaf(w0, u0.z, a0.z); a0.w = fmaf(w0, u0.w, a0.w);
            a1.x = fmaf(w0, u1.x, a1.x); a1.y = fmaf(w0, u1.y, a1.y);
            a1.z = fmaf(w0, u1.z, a1.z); a1.w = fmaf(w0, u1.w, a1.w);
        }
        out[(size_t)r * 64 + lane] = a0;
        out[(size_t)r * 64 + 32 + lane] = a1;
        s0.x += a0.x; s0.y += a0.y; s0.z += a0.z; s0.w += a0.w;
        s1.x += a1.x; s1.y += a1.y; s1.z += a1.z; s1.w += a1.w;
        q0.x = fmaf(a0.x, a0.x, q0.x); q0.y = fmaf(a0.y, a0.y, q0.y);
        q0.z = fmaf(a0.z, a0.z, q0.z); q0.w = fmaf(a0.w, a0.w, q0.w);
        q1.x = fmaf(a1.x, a1.x, q1.x); q1.y = fmaf(a1.y, a1.y, q1.y);
        q1.z = fmaf(a1.z, a1.z, q1.z); q1.w = fmaf(a1.w, a1.w, q1.w);
    }

    // CTA reduction of stats: slot layout [warp][float4-col 0..63]
    sm_s[w][lane]      = s0;  sm_s[w][lane + 32] = s1;
    sm_q[w][lane]      = q0;  sm_q[w][lane + 32] = q1;
    __syncthreads();

    int t = threadIdx.x;
    if (t < 64) {               // sum slots
        float4 acc = sm_s[0][t];
        #pragma unroll
        for (int ww = 1; ww < 8; ww++) {
            float4 v = sm_s[ww][t];
            acc.x += v.x; acc.y += v.y; acc.z += v.z; acc.w += v.w;
        }
        int c = t * 4;
        atomicAdd(&g_sum[c + 0], acc.x); atomicAdd(&g_sum[c + 1], acc.y);
        atomicAdd(&g_sum[c + 2], acc.z); atomicAdd(&g_sum[c + 3], acc.w);
    } else if (t < 128) {       // sumsq slots
        int sl = t - 64;
        float4 acc = sm_q[0][sl];
        #pragma unroll
        for (int ww = 1; ww < 8; ww++) {
            float4 v = sm_q[ww][sl];
            acc.x += v.x; acc.y += v.y; acc.z += v.z; acc.w += v.w;
        }
        int c = sl * 4;
        atomicAdd(&g_sumsq[c + 0], acc.x); atomicAdd(&g_sumsq[c + 1], acc.y);
        atomicAdd(&g_sumsq[c + 2], acc.z); atomicAdd(&g_sumsq[c + 3], acc.w);
    }
}

// Fold BN into y = x*scale + shift; reset accumulators for the next layer.
__global__ void finalize_kernel(const float* __restrict__ gamma,
                                const float* __restrict__ beta, float invN) {
    int c = threadIdx.x;
    float m = g_sum[c] * invN;
    float var = g_sumsq[c] * invN - m * m;
    float rs = rsqrtf(var + EPSV);
    float sc = rs * gamma[c];
    g_scale[c] = sc;
    g_shift[c] = beta[c] - m * sc;
    g_sum[c] = 0.f;
    g_sumsq[c] = 0.f;
}

// ---------------------------------------------------------------------------
// tf32 tensor-core GEMM: C = op(A) @ B (+ bias); op(A) = optional gather +
// optional BN+ReLU applied at smem-store time. CTA tile 128x64, K-tile 32,
// 8 warps (4x2), each 32x32 via 2x4 m16n8k8 tf32 mma fragments.
// ---------------------------------------------------------------------------
__global__ __launch_bounds__(256) void gemm_tf32(
    const float* __restrict__ A, const float* __restrict__ B,
    const float* __restrict__ bias, const int* __restrict__ gather,
    int use_bn, float* __restrict__ C, int M, int Ncols, int K)
{
    __shared__ __align__(16) float As[128 * 36];
    __shared__ __align__(16) float Bs[32 * 72];

    int tid = threadIdx.x;
    int lane = tid & 31, w = tid >> 5;
    int wm = w >> 1, wn = w & 1;
    int g = lane >> 2, tg = lane & 3;
    int row0 = blockIdx.y * 128, col0 = blockIdx.x * 64;

    float acc[2][4][4];
    #pragma unroll
    for (int mi = 0; mi < 2; mi++)
        #pragma unroll
        for (int ni = 0; ni < 4; ni++)
            #pragma unroll
            for (int j = 0; j < 4; j++) acc[mi][ni][j] = 0.f;

    int asrc[4];
    #pragma unroll
    for (int p = 0; p < 4; p++) {
        int idx = tid + p * 256;
        int grow = row0 + (idx >> 3);
        int sr = grow < M ? grow : M - 1;
        if (gather) sr = __ldg(gather + sr);
        asrc[p] = sr;
    }

    for (int kt = 0; kt < K; kt += 32) {
        #pragma unroll
        for (int p = 0; p < 4; p++) {
            int idx = tid + p * 256;
            int row = idx >> 3, c4 = idx & 7;
            int cb = kt + c4 * 4;
            float4 v = *reinterpret_cast<const float4*>(A + (size_t)asrc[p] * K + cb);
            if (use_bn) {
                v.x = fmaxf(fmaf(v.x, g_scale[cb + 0], g_shift[cb + 0]), 0.f);
                v.y = fmaxf(fmaf(v.y, g_scale[cb + 1], g_shift[cb + 1]), 0.f);
                v.z = fmaxf(fmaf(v.z, g_scale[cb + 2], g_shift[cb + 2]), 0.f);
                v.w = fmaxf(fmaf(v.w, g_scale[cb + 3], g_shift[cb + 3]), 0.f);
            }
            float4 o;
            o.x = __uint_as_float(f2tf(v.x));
            o.y = __uint_as_float(f2tf(v.y));
            o.z = __uint_as_float(f2tf(v.z));
            o.w = __uint_as_float(f2tf(v.w));
            *reinterpret_cast<float4*>(As + row * 36 + c4 * 4) = o;
        }
        #pragma unroll
        for (int p = 0; p < 2; p++) {
            int idx = tid + p * 256;
            int row = idx >> 4, c4 = idx & 15;
            float4 v = *reinterpret_cast<const float4*>(
                B + (size_t)(kt + row) * Ncols + col0 + c4 * 4);
            float4 o;
            o.x = __uint_as_float(f2tf(v.x));
            o.y = __uint_as_float(f2tf(v.y));
            o.z = __uint_as_float(f2tf(v.z));
            o.w = __uint_as_float(f2tf(v.w));
            *reinterpret_cast<float4*>(Bs + row * 72 + c4 * 4) = o;
        }
        __syncthreads();

        #pragma unroll
        for (int kk = 0; kk < 4; kk++) {
            unsigned a[2][4], b[4][2];
            #pragma unroll
            for (int mi = 0; mi < 2; mi++) {
                int rb = wm * 32 + mi * 16;
                int kc = kk * 8 + tg;
                a[mi][0] = __float_as_uint(As[(rb + g)     * 36 + kc]);
                a[mi][1] = __float_as_uint(As[(rb + g + 8) * 36 + kc]);
                a[mi][2] = __float_as_uint(As[(rb + g)     * 36 + kc + 4]);
                a[mi][3] = __float_as_uint(As[(rb + g + 8) * 36 + kc + 4]);
            }
            #pragma unroll
            for (int ni = 0; ni < 4; ni++) {
                int col = wn * 32 + ni * 8 + g;
                b[ni][0] = __float_as_uint(Bs[(kk * 8 + tg)     * 72 + col]);
                b[ni][1] = __float_as_uint(Bs[(kk * 8 + tg + 4) * 72 + col]);
            }
            #pragma unroll
            for (int mi = 0; mi < 2; mi++)
                #pragma unroll
                for (int ni = 0; ni < 4; ni++)
                    asm volatile(
                        "mma.sync.aligned.m16n8k8.row.col.f32.tf32.tf32.f32 "
                        "{%0,%1,%2,%3}, {%4,%5,%6,%7}, {%8,%9}, {%0,%1,%2,%3};"
                        : "+f"(acc[mi][ni][0]), "+f"(acc[mi][ni][1]),
                          "+f"(acc[mi][ni][2]), "+f"(acc[mi][ni][3])
                        : "r"(a[mi][0]), "r"(a[mi][1]), "r"(a[mi][2]), "r"(a[mi][3]),
                          "r"(b[ni][0]), "r"(b[ni][1]));
        }
        __syncthreads();
    }

    #pragma unroll
    for (int mi = 0; mi < 2; mi++) {
        int r = row0 + wm * 32 + mi * 16 + g;
        #pragma unroll
        for (int ni = 0; ni < 4; ni++) {
            int c = col0 + wn * 32 + ni * 8 + tg * 2;
            float bx = bias ? __ldg(bias + c) : 0.f;
            float by = bias ? __ldg(bias + c + 1) : 0.f;
            if (r < M) {
                float2 o = make_float2(acc[mi][ni][0] + bx, acc[mi][ni][1] + by);
                *reinterpret_cast<float2*>(C + (size_t)r * Ncols + c) = o;
            }
            if (r + 8 < M) {
                float2 o = make_float2(acc[mi][ni][2] + bx, acc[mi][ni][3] + by);
                *reinterpret_cast<float2*>(C + (size_t)(r + 8) * Ncols + c) = o;
            }
        }
    }
}

// ---------------------------------------------------------------------------
// Launch sequence (graph-capturable: kernels only).
// ---------------------------------------------------------------------------
extern "C" void kernel_launch(void* const* d_in, const int* in_sizes, int n_in,
                              void* d_out, int out_size) {
    const float* features  = (const float*)d_in[0];
    const float* edge_vals = (const float*)d_in[1];
    const float* W1  = (const float*)d_in[2];
    const float* db1 = (const float*)d_in[3];
    // d_in[4] = b1  : cancels in BatchNorm
    const float* g1  = (const float*)d_in[5];
    const float* be1 = (const float*)d_in[6];
    const float* W2  = (const float*)d_in[7];
    // d_in[8] = b2  : cancels in BatchNorm
    const float* g2  = (const float*)d_in[9];
    const float* be2 = (const float*)d_in[10];
    const float* Wf  = (const float*)d_in[11];
    const float* bf  = (const float*)d_in[12];
    const int* erows = (const int*)d_in[13];
    const int* ecols = (const int*)d_in[14];
    const int* idx   = (const int*)d_in[15];
    float* out = (float*)d_out;

    int N = in_sizes[0] / FDIM;   // 50000
    int E = in_sizes[1];          // 800000
    int M = in_sizes[15];         // 25000
    float invN = 1.0f / (float)N;

    float *b0, *b1;
    cudaGetSymbolAddress((void**)&b0, g_buf0);
    cudaGetSymbolAddress((void**)&b1, g_buf1);

    int eblocks = (E + 255) / 256;
    dim3 ggrid(FDIM / 64, (N + 127) / 128);
    int spmm_blocks = (N + 8 * RPW - 1) / (8 * RPW);

    // CSR build (shared by both spmms)
    init_kernel<<<(N + 255) / 256, 256>>>(N);
    hist_kernel<<<eblocks, 256>>>(erows, E);
    scan_kernel<<<1, 1024>>>(N, E);
    scatter_kernel<<<eblocks, 256>>>(erows, ecols, edge_vals, E);

    // layer 1
    gemm_tf32<<<ggrid, 256>>>(features, W1, db1, nullptr, 0, b0, N, FDIM, FDIM);
    spmm_csr<<<spmm_blocks, 256>>>((const float4*)b0, (float4*)b1, N);
    finalize_kernel<<<1, 256>>>(g1, be1, invN);

    // layer 2 (BN1+ReLU fused into A-load)
    gemm_tf32<<<ggrid, 256>>>(b1, W2, nullptr, nullptr, 1, b0, N, FDIM, FDIM);
    spmm_csr<<<spmm_blocks, 256>>>((const float4*)b0, (float4*)b1, N);
    finalize_kernel<<<1, 256>>>(g2, be2, invN);

    // head (BN2+ReLU + gather fused into A-load)
    gemm_tf32<<<dim3(128 / 64, (M + 127) / 128), 256>>>(
        b1, Wf, bf, idx, 1, out, M, 128, FDIM);
}

// round 4
// speedup vs baseline: 2.2571x; 1.1672x over previous
#include <cuda_runtime.h>
#include <cuda_bf16.h>

// ---------------------------------------------------------------------------
// GCN forward, round 4:
//   - hierarchical warp-shuffle scan for CSR row pointers (was ~70us naive)
//   - software-pipelined tf32 GEMM (register prefetch of next K-tile)
//   - CSR SpMM with fused BN stats (unchanged from round 3)
// ---------------------------------------------------------------------------

#define NMAXN 50000
#define EMAX  800000
#define FDIM  256
#define EPSV  1e-5f
#define RPW   10          // rows per warp in spmm_csr

__device__ float g_buf0[(size_t)NMAXN * FDIM];
__device__ float g_buf1[(size_t)NMAXN * FDIM];
__device__ float g_sum[FDIM];
__device__ float g_sumsq[FDIM];
__device__ float g_scale[FDIM];
__device__ float g_shift[FDIM];

__device__ int   g_cnt[NMAXN];       // histogram
__device__ int   g_cursor[NMAXN];    // scatter cursors
__device__ int   g_ptr[NMAXN + 1];   // CSR row pointers
__device__ int   g_blk[64];          // block partial sums for scan
__device__ int   g_ccol[EMAX];       // CSR cols
__device__ float g_cval[EMAX];       // CSR vals

__device__ __forceinline__ unsigned f2tf(float f) {
    unsigned u;
    asm("cvt.rna.tf32.f32 %0, %1;" : "=r"(u) : "f"(f));
    return u;
}

// ---------------------------------------------------------------------------
// CSR build
// ---------------------------------------------------------------------------
__global__ void init_kernel(int n) {
    int i = blockIdx.x * blockDim.x + threadIdx.x;
    if (i < n) g_cnt[i] = 0;
}

__global__ void hist_kernel(const int* __restrict__ er, int E) {
    int e = blockIdx.x * blockDim.x + threadIdx.x;
    if (e < E) atomicAdd(&g_cnt[er[e]], 1);
}

// Block-local exclusive scan (1024 threads, warp shuffles); block totals to g_blk.
__global__ __launch_bounds__(1024) void scan1_kernel(int n) {
    __shared__ int wsum[32];
    int tid = threadIdx.x;
    int i = blockIdx.x * 1024 + tid;
    int lane = tid & 31, wid = tid >> 5;
    int v = (i < n) ? g_cnt[i] : 0;
    int x = v;
    #pragma unroll
    for (int d = 1; d < 32; d <<= 1) {
        int t = __shfl_up_sync(0xffffffffu, x, d);
        if (lane >= d) x += t;
    }
    if (lane == 31) wsum[wid] = x;
    __syncthreads();
    if (wid == 0) {
        int y = wsum[lane];
        #pragma unroll
        for (int d = 1; d < 32; d <<= 1) {
            int t = __shfl_up_sync(0xffffffffu, y, d);
            if (lane >= d) y += t;
        }
        wsum[lane] = y;
    }
    __syncthreads();
    int incl = x + (wid > 0 ? wsum[wid - 1] : 0);
    if (i < n) g_ptr[i] = incl - v;         // block-local exclusive
    if (tid == 1023) g_blk[blockIdx.x] = incl;  // block total
}

// Scan the (<=64) block totals with one warp + serial smem pass.
__global__ void scan2_kernel(int nb) {
    __shared__ int s[64];
    int tid = threadIdx.x;
    if (tid < 64) s[tid] = (tid < nb) ? g_blk[tid] : 0;
    __syncthreads();
    if (tid == 0) {
        int acc = 0;
        for (int i = 0; i < nb; i++) { int t = s[i]; s[i] = acc; acc += t; }
    }
    __syncthreads();
    if (tid < nb) g_blk[tid] = s[tid];
}

// Add block offsets, write cursors, finish ptr[n], reset BN stat accumulators.
__global__ __launch_bounds__(1024) void scan3_kernel(int n, int E) {
    int i = blockIdx.x * 1024 + threadIdx.x;
    if (i < n) {
        int p = g_ptr[i] + g_blk[i >> 10];
        g_ptr[i] = p;
        g_cursor[i] = p;
    }
    if (i == 0) g_ptr[n] = E;
    if (i < FDIM) { g_sum[i] = 0.f; g_sumsq[i] = 0.f; }
}

__global__ void scatter_kernel(const int* __restrict__ er, const int* __restrict__ ec,
                               const float* __restrict__ ev, int E) {
    int e = blockIdx.x * blockDim.x + threadIdx.x;
    if (e >= E) return;
    int pos = atomicAdd(&g_cursor[er[e]], 1);
    g_ccol[pos] = ec[e];
    g_cval[pos] = ev[e];
}

// ---------------------------------------------------------------------------
// CSR SpMM with fused BN statistics (one warp per RPW rows, register accum,
// plain float4 stores; CTA-level stat reduction -> one atomic set per CTA).
// ---------------------------------------------------------------------------
__global__ __launch_bounds__(256) void spmm_csr(
    const float4* __restrict__ x, float4* __restrict__ out, int N)
{
    __shared__ __align__(16) float4 sm_s[8][64];
    __shared__ __align__(16) float4 sm_q[8][64];

    int lane = threadIdx.x & 31;
    int w = threadIdx.x >> 5;
    int r0 = (blockIdx.x * 8 + w) * RPW;

    float4 s0 = {0,0,0,0}, q0 = {0,0,0,0};
    float4 s1 = {0,0,0,0}, q1 = {0,0,0,0};

    int rend = min(r0 + RPW, N);
    for (int r = r0; r < rend; r++) {
        int e = __ldg(&g_ptr[r]);
        int end = __ldg(&g_ptr[r + 1]);
        float4 a0 = {0,0,0,0}, a1 = {0,0,0,0};
        for (; e + 1 < end; e += 2) {
            int   c0 = __ldg(&g_ccol[e]),     c1 = __ldg(&g_ccol[e + 1]);
            float w0 = __ldg(&g_cval[e]),     w1 = __ldg(&g_cval[e + 1]);
            float4 u0 = __ldg(x + (size_t)c0 * 64 + lane);
            float4 u1 = __ldg(x + (size_t)c0 * 64 + 32 + lane);
            float4 v0 = __ldg(x + (size_t)c1 * 64 + lane);
            float4 v1 = __ldg(x + (size_t)c1 * 64 + 32 + lane);
            a0.x = fmaf(w0, u0.x, fmaf(w1, v0.x, a0.x));
            a0.y = fmaf(w0, u0.y, fmaf(w1, v0.y, a0.y));
            a0.z = fmaf(w0, u0.z, fmaf(w1, v0.z, a0.z));
            a0.w = fmaf(w0, u0.w, fmaf(w1, v0.w, a0.w));
            a1.x = fmaf(w0, u1.x, fmaf(w1, v1.x, a1.x));
            a1.y = fmaf(w0, u1.y, fmaf(w1, v1.y, a1.y));
            a1.z = fmaf(w0, u1.z, fmaf(w1, v1.z, a1.z));
            a1.w = fmaf(w0, u1.w, fmaf(w1, v1.w, a1.w));
        }
        if (e < end) {
            int   c0 = __ldg(&g_ccol[e]);
            float w0 = __ldg(&g_cval[e]);
            float4 u0 = __ldg(x + (size_t)c0 * 64 + lane);
            float4 u1 = __ldg(x + (size_t)c0 * 64 + 32 + lane);
            a0.x = fmaf(w0, u0.x, a0.x); a0.y = fmaf(w0, u0.y, a0.y);
            a0.z = fmaf(w0, u0.z, a0.z); a0.w = fmaf(w0, u0.w, a0.w);
            a1.x = fmaf(w0, u1.x, a1.x); a1.y = fmaf(w0, u1.y, a1.y);
            a1.z = fmaf(w0, u1.z, a1.z); a1.w = fmaf(w0, u1.w, a1.w);
        }
        out[(size_t)r * 64 + lane] = a0;
        out[(size_t)r * 64 + 32 + lane] = a1;
        s0.x += a0.x; s0.y += a0.y; s0.z += a0.z; s0.w += a0.w;
        s1.x += a1.x; s1.y += a1.y; s1.z += a1.z; s1.w += a1.w;
        q0.x = fmaf(a0.x, a0.x, q0.x); q0.y = fmaf(a0.y, a0.y, q0.y);
        q0.z = fmaf(a0.z, a0.z, q0.z); q0.w = fmaf(a0.w, a0.w, q0.w);
        q1.x = fmaf(a1.x, a1.x, q1.x); q1.y = fmaf(a1.y, a1.y, q1.y);
        q1.z = fmaf(a1.z, a1.z, q1.z); q1.w = fmaf(a1.w, a1.w, q1.w);
    }

    sm_s[w][lane]      = s0;  sm_s[w][lane + 32] = s1;
    sm_q[w][lane]      = q0;  sm_q[w][lane + 32] = q1;
    __syncthreads();

    int t = threadIdx.x;
    if (t < 64) {
        float4 acc = sm_s[0][t];
        #pragma unroll
        for (int ww = 1; ww < 8; ww++) {
            float4 v = sm_s[ww][t];
            acc.x += v.x; acc.y += v.y; acc.z += v.z; acc.w += v.w;
        }
        int c = t * 4;
        atomicAdd(&g_sum[c + 0], acc.x); atomicAdd(&g_sum[c + 1], acc.y);
        atomicAdd(&g_sum[c + 2], acc.z); atomicAdd(&g_sum[c + 3], acc.w);
    } else if (t < 128) {
        int sl = t - 64;
        float4 acc = sm_q[0][sl];
        #pragma unroll
        for (int ww = 1; ww < 8; ww++) {
            float4 v = sm_q[ww][sl];
            acc.x += v.x; acc.y += v.y; acc.z += v.z; acc.w += v.w;
        }
        int c = sl * 4;
        atomicAdd(&g_sumsq[c + 0], acc.x); atomicAdd(&g_sumsq[c + 1], acc.y);
        atomicAdd(&g_sumsq[c + 2], acc.z); atomicAdd(&g_sumsq[c + 3], acc.w);
    }
}

// Fold BN into y = x*scale + shift; reset accumulators for next layer.
__global__ void finalize_kernel(const float* __restrict__ gamma,
                                const float* __restrict__ beta, float invN) {
    int c = threadIdx.x;
    float m = g_sum[c] * invN;
    float var = g_sumsq[c] * invN - m * m;
    float rs = rsqrtf(var + EPSV);
    float sc = rs * gamma[c];
    g_scale[c] = sc;
    g_shift[c] = beta[c] - m * sc;
    g_sum[c] = 0.f;
    g_sumsq[c] = 0.f;
}

// ---------------------------------------------------------------------------
// Software-pipelined tf32 GEMM: C = op(A) @ B (+ bias).
// Next K-tile prefetched into registers while MMAs consume current smem tile.
// ---------------------------------------------------------------------------
__global__ __launch_bounds__(256) void gemm_tf32(
    const float* __restrict__ A, const float* __restrict__ B,
    const float* __restrict__ bias, const int* __restrict__ gather,
    int use_bn, float* __restrict__ C, int M, int Ncols, int K)
{
    __shared__ __align__(16) float As[128 * 36];
    __shared__ __align__(16) float Bs[32 * 72];

    int tid = threadIdx.x;
    int lane = tid & 31, w = tid >> 5;
    int wm = w >> 1, wn = w & 1;
    int g = lane >> 2, tg = lane & 3;
    int row0 = blockIdx.y * 128, col0 = blockIdx.x * 64;

    float acc[2][4][4];
    #pragma unroll
    for (int mi = 0; mi < 2; mi++)
        #pragma unroll
        for (int ni = 0; ni < 4; ni++)
            #pragma unroll
            for (int j = 0; j < 4; j++) acc[mi][ni][j] = 0.f;

    int asrc[4];
    #pragma unroll
    for (int p = 0; p < 4; p++) {
        int idx = tid + p * 256;
        int grow = row0 + (idx >> 3);
        int sr = grow < M ? grow : M - 1;
        if (gather) sr = __ldg(gather + sr);
        asrc[p] = sr;
    }

    // prologue: fetch tile 0 into registers
    float4 ra[4], rb[2];
    #pragma unroll
    for (int p = 0; p < 4; p++) {
        int idx = tid + p * 256;
        ra[p] = *reinterpret_cast<const float4*>(A + (size_t)asrc[p] * K + (idx & 7) * 4);
    }
    #pragma unroll
    for (int p = 0; p < 2; p++) {
        int idx = tid + p * 256;
        rb[p] = *reinterpret_cast<const float4*>(
            B + (size_t)(idx >> 4) * Ncols + col0 + (idx & 15) * 4);
    }

    for (int kt = 0; kt < K; kt += 32) {
        // store current regs to smem (BN + tf32 at store)
        #pragma unroll
        for (int p = 0; p < 4; p++) {
            int idx = tid + p * 256;
            int row = idx >> 3, c4 = idx & 7;
            int cb = kt + c4 * 4;
            float4 v = ra[p];
            if (use_bn) {
                v.x = fmaxf(fmaf(v.x, g_scale[cb + 0], g_shift[cb + 0]), 0.f);
                v.y = fmaxf(fmaf(v.y, g_scale[cb + 1], g_shift[cb + 1]), 0.f);
                v.z = fmaxf(fmaf(v.z, g_scale[cb + 2], g_shift[cb + 2]), 0.f);
                v.w = fmaxf(fmaf(v.w, g_scale[cb + 3], g_shift[cb + 3]), 0.f);
            }
            float4 o;
            o.x = __uint_as_float(f2tf(v.x));
            o.y = __uint_as_float(f2tf(v.y));
            o.z = __uint_as_float(f2tf(v.z));
            o.w = __uint_as_float(f2tf(v.w));
            *reinterpret_cast<float4*>(As + row * 36 + c4 * 4) = o;
        }
        #pragma unroll
        for (int p = 0; p < 2; p++) {
            int idx = tid + p * 256;
            int row = idx >> 4, c4 = idx & 15;
            float4 v = rb[p];
            float4 o;
            o.x = __uint_as_float(f2tf(v.x));
            o.y = __uint_as_float(f2tf(v.y));
            o.z = __uint_as_float(f2tf(v.z));
            o.w = __uint_as_float(f2tf(v.w));
            *reinterpret_cast<float4*>(Bs + row * 72 + c4 * 4) = o;
        }
        __syncthreads();

        // prefetch next tile into registers (hidden behind MMAs)
        int ktn = kt + 32;
        if (ktn < K) {
            #pragma unroll
            for (int p = 0; p < 4; p++) {
                int idx = tid + p * 256;
                ra[p] = *reinterpret_cast<const float4*>(
                    A + (size_t)asrc[p] * K + ktn + (idx & 7) * 4);
            }
            #pragma unroll
            for (int p = 0; p < 2; p++) {
                int idx = tid + p * 256;
                rb[p] = *reinterpret_cast<const float4*>(
                    B + (size_t)(ktn + (idx >> 4)) * Ncols + col0 + (idx & 15) * 4);
            }
        }

        #pragma unroll
        for (int kk = 0; kk < 4; kk++) {
            unsigned a[2][4], b[4][2];
            #pragma unroll
            for (int mi = 0; mi < 2; mi++) {
                int rb_ = wm * 32 + mi * 16;
                int kc = kk * 8 + tg;
                a[mi][0] = __float_as_uint(As[(rb_ + g)     * 36 + kc]);
                a[mi][1] = __float_as_uint(As[(rb_ + g + 8) * 36 + kc]);
                a[mi][2] = __float_as_uint(As[(rb_ + g)     * 36 + kc + 4]);
                a[mi][3] = __float_as_uint(As[(rb_ + g + 8) * 36 + kc + 4]);
            }
            #pragma unroll
            for (int ni = 0; ni < 4; ni++) {
                int col = wn * 32 + ni * 8 + g;
                b[ni][0] = __float_as_uint(Bs[(kk * 8 + tg)     * 72 + col]);
                b[ni][1] = __float_as_uint(Bs[(kk * 8 + tg + 4) * 72 + col]);
            }
            #pragma unroll
            for (int mi = 0; mi < 2; mi++)
                #pragma unroll
                for (int ni = 0; ni < 4; ni++)
                    asm volatile(
                        "mma.sync.aligned.m16n8k8.row.col.f32.tf32.tf32.f32 "
                        "{%0,%1,%2,%3}, {%4,%5,%6,%7}, {%8,%9}, {%0,%1,%2,%3};"
                        : "+f"(acc[mi][ni][0]), "+f"(acc[mi][ni][1]),
                          "+f"(acc[mi][ni][2]), "+f"(acc[mi][ni][3])
                        : "r"(a[mi][0]), "r"(a[mi][1]), "r"(a[mi][2]), "r"(a[mi][3]),
                          "r"(b[ni][0]), "r"(b[ni][1]));
        }
        __syncthreads();
    }

    #pragma unroll
    for (int mi = 0; mi < 2; mi++) {
        int r = row0 + wm * 32 + mi * 16 + g;
        #pragma unroll
        for (int ni = 0; ni < 4; ni++) {
            int c = col0 + wn * 32 + ni * 8 + tg * 2;
            float bx = bias ? __ldg(bias + c) : 0.f;
            float by = bias ? __ldg(bias + c + 1) : 0.f;
            if (r < M) {
                float2 o = make_float2(acc[mi][ni][0] + bx, acc[mi][ni][1] + by);
                *reinterpret_cast<float2*>(C + (size_t)r * Ncols + c) = o;
            }
            if (r + 8 < M) {
                float2 o = make_float2(acc[mi][ni][2] + bx, acc[mi][ni][3] + by);
                *reinterpret_cast<float2*>(C + (size_t)(r + 8) * Ncols + c) = o;
            }
        }
    }
}

// ---------------------------------------------------------------------------
// Launch sequence (graph-capturable: kernels only).
// ---------------------------------------------------------------------------
extern "C" void kernel_launch(void* const* d_in, const int* in_sizes, int n_in,
                              void* d_out, int out_size) {
    const float* features  = (const float*)d_in[0];
    const float* edge_vals = (const float*)d_in[1];
    const float* W1  = (const float*)d_in[2];
    const float* db1 = (const float*)d_in[3];
    // d_in[4] = b1  : cancels in BatchNorm
    const float* g1  = (const float*)d_in[5];
    const float* be1 = (const float*)d_in[6];
    const float* W2  = (const float*)d_in[7];
    // d_in[8] = b2  : cancels in BatchNorm
    const float* g2  = (const float*)d_in[9];
    const float* be2 = (const float*)d_in[10];
    const float* Wf  = (const float*)d_in[11];
    const float* bf  = (const float*)d_in[12];
    const int* erows = (const int*)d_in[13];
    const int* ecols = (const int*)d_in[14];
    const int* idx   = (const int*)d_in[15];
    float* out = (float*)d_out;

    int N = in_sizes[0] / FDIM;   // 50000
    int E = in_sizes[1];          // 800000
    int M = in_sizes[15];         // 25000
    float invN = 1.0f / (float)N;

    float *b0, *b1;
    cudaGetSymbolAddress((void**)&b0, g_buf0);
    cudaGetSymbolAddress((void**)&b1, g_buf1);

    int eblocks = (E + 255) / 256;
    int nb = (N + 1023) / 1024;
    dim3 ggrid(FDIM / 64, (N + 127) / 128);
    int spmm_blocks = (N + 8 * RPW - 1) / (8 * RPW);

    // CSR build (shared by both spmms)
    init_kernel<<<(N + 255) / 256, 256>>>(N);
    hist_kernel<<<eblocks, 256>>>(erows, E);
    scan1_kernel<<<nb, 1024>>>(N);
    scan2_kernel<<<1, 64>>>(nb);
    scan3_kernel<<<nb, 1024>>>(N, E);
    scatter_kernel<<<eblocks, 256>>>(erows, ecols, edge_vals, E);

    // layer 1
    gemm_tf32<<<ggrid, 256>>>(features, W1, db1, nullptr, 0, b0, N, FDIM, FDIM);
    spmm_csr<<<spmm_blocks, 256>>>((const float4*)b0, (float4*)b1, N);
    finalize_kernel<<<1, 256>>>(g1, be1, invN);

    // layer 2 (BN1+ReLU fused into A-load)
    gemm_tf32<<<ggrid, 256>>>(b1, W2, nullptr, nullptr, 1, b0, N, FDIM, FDIM);
    spmm_csr<<<spmm_blocks, 256>>>((const float4*)b0, (float4*)b1, N);
    finalize_kernel<<<1, 256>>>(g2, be2, invN);

    // head (BN2+ReLU + gather fused into A-load)
    gemm_tf32<<<dim3(128 / 64, (M + 127) / 128), 256>>>(
        b1, Wf, bf, idx, 1, out, M, 128, FDIM);
}

// round 6
// speedup vs baseline: 2.4655x; 1.0924x over previous
#include <cuda_runtime.h>
#include <cuda_fp16.h>

// ---------------------------------------------------------------------------
// GCN forward, round 6 (= round 5 with the spmm fp16 row-stride bug fixed):
//   - GEMM1/2 emit fp16 activations (only consumer is SpMM gather)
//   - SpMM gathers half rows (400MB vs 800MB L2 traffic), fp32 accum/output
//   - hierarchical scan CSR build, fused BN stats, pipelined tf32 GEMM
// ---------------------------------------------------------------------------

#define NMAXN 50000
#define EMAX  800000
#define FDIM  256
#define EPSV  1e-5f
#define RPW   10          // rows per warp in spmm_csr

__device__ __half g_hbuf[(size_t)NMAXN * FDIM];   // fp16 gemm output
__device__ float  g_buf1[(size_t)NMAXN * FDIM];   // fp32 spmm output
__device__ float  g_sum[FDIM];
__device__ float  g_sumsq[FDIM];
__device__ float  g_scale[FDIM];
__device__ float  g_shift[FDIM];

__device__ int   g_cnt[NMAXN];
__device__ int   g_cursor[NMAXN];
__device__ int   g_ptr[NMAXN + 1];
__device__ int   g_blk[64];
__device__ int   g_ccol[EMAX];
__device__ float g_cval[EMAX];

__device__ __forceinline__ unsigned f2tf(float f) {
    unsigned u;
    asm("cvt.rna.tf32.f32 %0, %1;" : "=r"(u) : "f"(f));
    return u;
}

// ---------------------------------------------------------------------------
// CSR build
// ---------------------------------------------------------------------------
__global__ void init_kernel(int n) {
    int i = blockIdx.x * blockDim.x + threadIdx.x;
    if (i < n) g_cnt[i] = 0;
}

__global__ void hist_kernel(const int* __restrict__ er, int E) {
    int e = blockIdx.x * blockDim.x + threadIdx.x;
    if (e < E) atomicAdd(&g_cnt[er[e]], 1);
}

__global__ __launch_bounds__(1024) void scan1_kernel(int n) {
    __shared__ int wsum[32];
    int tid = threadIdx.x;
    int i = blockIdx.x * 1024 + tid;
    int lane = tid & 31, wid = tid >> 5;
    int v = (i < n) ? g_cnt[i] : 0;
    int x = v;
    #pragma unroll
    for (int d = 1; d < 32; d <<= 1) {
        int t = __shfl_up_sync(0xffffffffu, x, d);
        if (lane >= d) x += t;
    }
    if (lane == 31) wsum[wid] = x;
    __syncthreads();
    if (wid == 0) {
        int y = wsum[lane];
        #pragma unroll
        for (int d = 1; d < 32; d <<= 1) {
            int t = __shfl_up_sync(0xffffffffu, y, d);
            if (lane >= d) y += t;
        }
        wsum[lane] = y;
    }
    __syncthreads();
    int incl = x + (wid > 0 ? wsum[wid - 1] : 0);
    if (i < n) g_ptr[i] = incl - v;
    if (tid == 1023) g_blk[blockIdx.x] = incl;
}

__global__ void scan2_kernel(int nb) {
    __shared__ int s[64];
    int tid = threadIdx.x;
    if (tid < 64) s[tid] = (tid < nb) ? g_blk[tid] : 0;
    __syncthreads();
    if (tid == 0) {
        int acc = 0;
        for (int i = 0; i < nb; i++) { int t = s[i]; s[i] = acc; acc += t; }
    }
    __syncthreads();
    if (tid < nb) g_blk[tid] = s[tid];
}

__global__ __launch_bounds__(1024) void scan3_kernel(int n, int E) {
    int i = blockIdx.x * 1024 + threadIdx.x;
    if (i < n) {
        int p = g_ptr[i] + g_blk[i >> 10];
        g_ptr[i] = p;
        g_cursor[i] = p;
    }
    if (i == 0) g_ptr[n] = E;
    if (i < FDIM) { g_sum[i] = 0.f; g_sumsq[i] = 0.f; }
}

__global__ void scatter_kernel(const int* __restrict__ er, const int* __restrict__ ec,
                               const float* __restrict__ ev, int E) {
    int e = blockIdx.x * blockDim.x + threadIdx.x;
    if (e >= E) return;
    int pos = atomicAdd(&g_cursor[er[e]], 1);
    g_ccol[pos] = ec[e];
    g_cval[pos] = ev[e];
}

// ---------------------------------------------------------------------------
// CSR SpMM (fp16 gather -> fp32 accum/output) with fused BN statistics.
// Lane owns 8 consecutive columns (one uint4 = 8 halves per row-gather).
// Row stride: 256 halves = 32 uint4.  <-- round-5 bug was *16 here.
// ---------------------------------------------------------------------------
__global__ __launch_bounds__(256) void spmm_csr(
    const uint4* __restrict__ x, float4* __restrict__ out, int N)
{
    __shared__ __align__(16) float4 sm_s[8][64];
    __shared__ __align__(16) float4 sm_q[8][64];

    int lane = threadIdx.x & 31;
    int w = threadIdx.x >> 5;
    int r0 = (blockIdx.x * 8 + w) * RPW;

    float s[8] = {}, q[8] = {};

    int rend = min(r0 + RPW, N);
    for (int r = r0; r < rend; r++) {
        int e = __ldg(&g_ptr[r]);
        int end = __ldg(&g_ptr[r + 1]);
        float a[8] = {};
        for (; e + 1 < end; e += 2) {
            int   c0 = __ldg(&g_ccol[e]),  c1 = __ldg(&g_ccol[e + 1]);
            float w0 = __ldg(&g_cval[e]),  w1 = __ldg(&g_cval[e + 1]);
            uint4 u = __ldg(x + (size_t)c0 * 32 + lane);
            uint4 v = __ldg(x + (size_t)c1 * 32 + lane);
            const unsigned* up = &u.x;
            const unsigned* vp = &v.x;
            #pragma unroll
            for (int j = 0; j < 4; j++) {
                float2 fu = __half22float2(*reinterpret_cast<const __half2*>(&up[j]));
                float2 fv = __half22float2(*reinterpret_cast<const __half2*>(&vp[j]));
                a[j * 2 + 0] = fmaf(w0, fu.x, fmaf(w1, fv.x, a[j * 2 + 0]));
                a[j * 2 + 1] = fmaf(w0, fu.y, fmaf(w1, fv.y, a[j * 2 + 1]));
            }
        }
        if (e < end) {
            int   c0 = __ldg(&g_ccol[e]);
            float w0 = __ldg(&g_cval[e]);
            uint4 u = __ldg(x + (size_t)c0 * 32 + lane);
            const unsigned* up = &u.x;
            #pragma unroll
            for (int j = 0; j < 4; j++) {
                float2 fu = __half22float2(*reinterpret_cast<const __half2*>(&up[j]));
                a[j * 2 + 0] = fmaf(w0, fu.x, a[j * 2 + 0]);
                a[j * 2 + 1] = fmaf(w0, fu.y, a[j * 2 + 1]);
            }
        }
        // store row (lane covers cols lane*8 .. lane*8+7) and update stats
        float4 o0 = make_float4(a[0], a[1], a[2], a[3]);
        float4 o1 = make_float4(a[4], a[5], a[6], a[7]);
        out[(size_t)r * 64 + lane * 2]     = o0;
        out[(size_t)r * 64 + lane * 2 + 1] = o1;
        #pragma unroll
        for (int j = 0; j < 8; j++) {
            s[j] += a[j];
            q[j] = fmaf(a[j], a[j], q[j]);
        }
    }

    sm_s[w][lane * 2]     = make_float4(s[0], s[1], s[2], s[3]);
    sm_s[w][lane * 2 + 1] = make_float4(s[4], s[5], s[6], s[7]);
    sm_q[w][lane * 2]     = make_float4(q[0], q[1], q[2], q[3]);
    sm_q[w][lane * 2 + 1] = make_float4(q[4], q[5], q[6], q[7]);
    __syncthreads();

    int t = threadIdx.x;
    if (t < 64) {
        float4 acc = sm_s[0][t];
        #pragma unroll
        for (int ww = 1; ww < 8; ww++) {
            float4 v = sm_s[ww][t];
            acc.x += v.x; acc.y += v.y; acc.z += v.z; acc.w += v.w;
        }
        int c = t * 4;
        atomicAdd(&g_sum[c + 0], acc.x); atomicAdd(&g_sum[c + 1], acc.y);
        atomicAdd(&g_sum[c + 2], acc.z); atomicAdd(&g_sum[c + 3], acc.w);
    } else if (t < 128) {
        int sl = t - 64;
        float4 acc = sm_q[0][sl];
        #pragma unroll
        for (int ww = 1; ww < 8; ww++) {
            float4 v = sm_q[ww][sl];
            acc.x += v.x; acc.y += v.y; acc.z += v.z; acc.w += v.w;
        }
        int c = sl * 4;
        atomicAdd(&g_sumsq[c + 0], acc.x); atomicAdd(&g_sumsq[c + 1], acc.y);
        atomicAdd(&g_sumsq[c + 2], acc.z); atomicAdd(&g_sumsq[c + 3], acc.w);
    }
}

__global__ void finalize_kernel(const float* __restrict__ gamma,
                                const float* __restrict__ beta, float invN) {
    int c = threadIdx.x;
    float m = g_sum[c] * invN;
    float var = g_sumsq[c] * invN - m * m;
    float rs = rsqrtf(var + EPSV);
    float sc = rs * gamma[c];
    g_scale[c] = sc;
    g_shift[c] = beta[c] - m * sc;
    g_sum[c] = 0.f;
    g_sumsq[c] = 0.f;
}

// ---------------------------------------------------------------------------
// Software-pipelined tf32 GEMM: C = op(A) @ B (+ bias).
// Output: fp16 (Ch != null) for spmm consumers, else fp32 (C).
// ---------------------------------------------------------------------------
__global__ __launch_bounds__(256) void gemm_tf32(
    const float* __restrict__ A, const float* __restrict__ B,
    const float* __restrict__ bias, const int* __restrict__ gather,
    int use_bn, float* __restrict__ C, __half* __restrict__ Ch,
    int M, int Ncols, int K)
{
    __shared__ __align__(16) float As[128 * 36];
    __shared__ __align__(16) float Bs[32 * 72];

    int tid = threadIdx.x;
    int lane = tid & 31, w = tid >> 5;
    int wm = w >> 1, wn = w & 1;
    int g = lane >> 2, tg = lane & 3;
    int row0 = blockIdx.y * 128, col0 = blockIdx.x * 64;

    float acc[2][4][4];
    #pragma unroll
    for (int mi = 0; mi < 2; mi++)
        #pragma unroll
        for (int ni = 0; ni < 4; ni++)
            #pragma unroll
            for (int j = 0; j < 4; j++) acc[mi][ni][j] = 0.f;

    int asrc[4];
    #pragma unroll
    for (int p = 0; p < 4; p++) {
        int idx = tid + p * 256;
        int grow = row0 + (idx >> 3);
        int sr = grow < M ? grow : M - 1;
        if (gather) sr = __ldg(gather + sr);
        asrc[p] = sr;
    }

    float4 ra[4], rb[2];
    #pragma unroll
    for (int p = 0; p < 4; p++) {
        int idx = tid + p * 256;
        ra[p] = *reinterpret_cast<const float4*>(A + (size_t)asrc[p] * K + (idx & 7) * 4);
    }
    #pragma unroll
    for (int p = 0; p < 2; p++) {
        int idx = tid + p * 256;
        rb[p] = *reinterpret_cast<const float4*>(
            B + (size_t)(idx >> 4) * Ncols + col0 + (idx & 15) * 4);
    }

    for (int kt = 0; kt < K; kt += 32) {
        #pragma unroll
        for (int p = 0; p < 4; p++) {
            int idx = tid + p * 256;
            int row = idx >> 3, c4 = idx & 7;
            int cb = kt + c4 * 4;
            float4 v = ra[p];
            if (use_bn) {
                v.x = fmaxf(fmaf(v.x, g_scale[cb + 0], g_shift[cb + 0]), 0.f);
                v.y = fmaxf(fmaf(v.y, g_scale[cb + 1], g_shift[cb + 1]), 0.f);
                v.z = fmaxf(fmaf(v.z, g_scale[cb + 2], g_shift[cb + 2]), 0.f);
                v.w = fmaxf(fmaf(v.w, g_scale[cb + 3], g_shift[cb + 3]), 0.f);
            }
            float4 o;
            o.x = __uint_as_float(f2tf(v.x));
            o.y = __uint_as_float(f2tf(v.y));
            o.z = __uint_as_float(f2tf(v.z));
            o.w = __uint_as_float(f2tf(v.w));
            *reinterpret_cast<float4*>(As + row * 36 + c4 * 4) = o;
        }
        #pragma unroll
        for (int p = 0; p < 2; p++) {
            int idx = tid + p * 256;
            int row = idx >> 4, c4 = idx & 15;
            float4 v = rb[p];
            float4 o;
            o.x = __uint_as_float(f2tf(v.x));
            o.y = __uint_as_float(f2tf(v.y));
            o.z = __uint_as_float(f2tf(v.z));
            o.w = __uint_as_float(f2tf(v.w));
            *reinterpret_cast<float4*>(Bs + row * 72 + c4 * 4) = o;
        }
        __syncthreads();

        int ktn = kt + 32;
        if (ktn < K) {
            #pragma unroll
            for (int p = 0; p < 4; p++) {
                int idx = tid + p * 256;
                ra[p] = *reinterpret_cast<const float4*>(
                    A + (size_t)asrc[p] * K + ktn + (idx & 7) * 4);
            }
            #pragma unroll
            for (int p = 0; p < 2; p++) {
                int idx = tid + p * 256;
                rb[p] = *reinterpret_cast<const float4*>(
                    B + (size_t)(ktn + (idx >> 4)) * Ncols + col0 + (idx & 15) * 4);
            }
        }

        #pragma unroll
        for (int kk = 0; kk < 4; kk++) {
            unsigned a[2][4], b[4][2];
            #pragma unroll
            for (int mi = 0; mi < 2; mi++) {
                int rb_ = wm * 32 + mi * 16;
                int kc = kk * 8 + tg;
                a[mi][0] = __float_as_uint(As[(rb_ + g)     * 36 + kc]);
                a[mi][1] = __float_as_uint(As[(rb_ + g + 8) * 36 + kc]);
                a[mi][2] = __float_as_uint(As[(rb_ + g)     * 36 + kc + 4]);
                a[mi][3] = __float_as_uint(As[(rb_ + g + 8) * 36 + kc + 4]);
            }
            #pragma unroll
            for (int ni = 0; ni < 4; ni++) {
                int col = wn * 32 + ni * 8 + g;
                b[ni][0] = __float_as_uint(Bs[(kk * 8 + tg)     * 72 + col]);
                b[ni][1] = __float_as_uint(Bs[(kk * 8 + tg + 4) * 72 + col]);
            }
            #pragma unroll
            for (int mi = 0; mi < 2; mi++)
                #pragma unroll
                for (int ni = 0; ni < 4; ni++)
                    asm volatile(
                        "mma.sync.aligned.m16n8k8.row.col.f32.tf32.tf32.f32 "
                        "{%0,%1,%2,%3}, {%4,%5,%6,%7}, {%8,%9}, {%0,%1,%2,%3};"
                        : "+f"(acc[mi][ni][0]), "+f"(acc[mi][ni][1]),
                          "+f"(acc[mi][ni][2]), "+f"(acc[mi][ni][3])
                        : "r"(a[mi][0]), "r"(a[mi][1]), "r"(a[mi][2]), "r"(a[mi][3]),
                          "r"(b[ni][0]), "r"(b[ni][1]));
        }
        __syncthreads();
    }

    #pragma unroll
    for (int mi = 0; mi < 2; mi++) {
        int r = row0 + wm * 32 + mi * 16 + g;
        #pragma unroll
        for (int ni = 0; ni < 4; ni++) {
            int c = col0 + wn * 32 + ni * 8 + tg * 2;
            float bx = bias ? __ldg(bias + c) : 0.f;
            float by = bias ? __ldg(bias + c + 1) : 0.f;
            float v0 = acc[mi][ni][0] + bx, v1 = acc[mi][ni][1] + by;
            float v2 = acc[mi][ni][2] + bx, v3 = acc[mi][ni][3] + by;
            if (Ch) {
                if (r < M)
                    *reinterpret_cast<__half2*>(Ch + (size_t)r * Ncols + c) =
                        __floats2half2_rn(v0, v1);
                if (r + 8 < M)
                    *reinterpret_cast<__half2*>(Ch + (size_t)(r + 8) * Ncols + c) =
                        __floats2half2_rn(v2, v3);
            } else {
                if (r < M)
                    *reinterpret_cast<float2*>(C + (size_t)r * Ncols + c) =
                        make_float2(v0, v1);
                if (r + 8 < M)
                    *reinterpret_cast<float2*>(C + (size_t)(r + 8) * Ncols + c) =
                        make_float2(v2, v3);
            }
        }
    }
}

// ---------------------------------------------------------------------------
// Launch sequence (graph-capturable: kernels only).
// ---------------------------------------------------------------------------
extern "C" void kernel_launch(void* const* d_in, const int* in_sizes, int n_in,
                              void* d_out, int out_size) {
    const float* features  = (const float*)d_in[0];
    const float* edge_vals = (const float*)d_in[1];
    const float* W1  = (const float*)d_in[2];
    const float* db1 = (const float*)d_in[3];
    // d_in[4] = b1  : cancels in BatchNorm
    const float* g1  = (const float*)d_in[5];
    const float* be1 = (const float*)d_in[6];
    const float* W2  = (const float*)d_in[7];
    // d_in[8] = b2  : cancels in BatchNorm
    const float* g2  = (const float*)d_in[9];
    const float* be2 = (const float*)d_in[10];
    const float* Wf  = (const float*)d_in[11];
    const float* bf  = (const float*)d_in[12];
    const int* erows = (const int*)d_in[13];
    const int* ecols = (const int*)d_in[14];
    const int* idx   = (const int*)d_in[15];
    float* out = (float*)d_out;

    int N = in_sizes[0] / FDIM;   // 50000
    int E = in_sizes[1];          // 800000
    int M = in_sizes[15];         // 25000
    float invN = 1.0f / (float)N;

    float *b1;
    __half *hb;
    cudaGetSymbolAddress((void**)&b1, g_buf1);
    cudaGetSymbolAddress((void**)&hb, g_hbuf);

    int eblocks = (E + 255) / 256;
    int nb = (N + 1023) / 1024;
    dim3 ggrid(FDIM / 64, (N + 127) / 128);
    int spmm_blocks = (N + 8 * RPW - 1) / (8 * RPW);

    // CSR build (shared by both spmms)
    init_kernel<<<(N + 255) / 256, 256>>>(N);
    hist_kernel<<<eblocks, 256>>>(erows, E);
    scan1_kernel<<<nb, 1024>>>(N);
    scan2_kernel<<<1, 64>>>(nb);
    scan3_kernel<<<nb, 1024>>>(N, E);
    scatter_kernel<<<eblocks, 256>>>(erows, ecols, edge_vals, E);

    // layer 1 (gemm -> fp16, spmm fp16->fp32 + stats)
    gemm_tf32<<<ggrid, 256>>>(features, W1, db1, nullptr, 0, nullptr, hb, N, FDIM, FDIM);
    spmm_csr<<<spmm_blocks, 256>>>((const uint4*)hb, (float4*)b1, N);
    finalize_kernel<<<1, 256>>>(g1, be1, invN);

    // layer 2 (BN1+ReLU fused into A-load; gemm -> fp16)
    gemm_tf32<<<ggrid, 256>>>(b1, W2, nullptr, nullptr, 1, nullptr, hb, N, FDIM, FDIM);
    spmm_csr<<<spmm_blocks, 256>>>((const uint4*)hb, (float4*)b1, N);
    finalize_kernel<<<1, 256>>>(g2, be2, invN);

    // head (BN2+ReLU + gather fused into A-load; fp32 out)
    gemm_tf32<<<dim3(128 / 64, (M + 127) / 128), 256>>>(
        b1, Wf, bf, idx, 1, out, nullptr, M, 128, FDIM);
}